// round 8
// baseline (speedup 1.0000x reference)
#include <cuda_runtime.h>

#define BB 2
#define NQv 1024
#define NKv 1024
#define DD 512
#define HH 32
#define H_SPLIT 26   // h <  H_SPLIT : XU tanh path
                     // h >= H_SPLIT : FMA-pipe rational path

// Scratch (no cudaMalloc allowed). Raw f32 projections.
__device__ __align__(16) float g_hk[BB * NKv * HH];   // keys@W1[:D] + b1
__device__ __align__(16) float g_hq[BB * NQv * HH];   // queries@W1[D:]

__device__ __forceinline__ float tanh_fast(float x) {
    float y; asm("tanh.approx.f32 %0, %1;" : "=f"(y) : "f"(x)); return y;
}
// FMA-pipe reciprocal: magic-seed (~3.4% rel) + 2 Newton -> ~1.4e-6 rel.
__device__ __forceinline__ float rcp_newton(float d) {
    float r = __uint_as_float(0x7EF311C3u - __float_as_uint(d));
    r = r * fmaf(-d, r, 2.0f);
    r = r * fmaf(-d, r, 2.0f);
    return r;
}

// ---------------------------------------------------------------------------
// Projection (R4 config, measured): C[2048,32] = A[2048,512] @ W[512,32]
// per tensor. Block = 256 thr, 32 rows, K chunked by 128, both operands in
// smem, thread = 4 rows x 1 h.
// ---------------------------------------------------------------------------
__global__ __launch_bounds__(256) void proj_kernel(
    const float* __restrict__ keys, const float* __restrict__ queries,
    const float* __restrict__ W1, const float* __restrict__ b1)
{
    __shared__ float as[32][128];   // A chunk (16 KB)
    __shared__ float ws[128][32];   // W chunk (16 KB)

    const int z    = blockIdx.y;
    const int tid  = threadIdx.x;
    const int h    = tid & 31;
    const int warp = tid >> 5;
    const int row0 = blockIdx.x * 32;
    const float* __restrict__ src = z ? queries : keys;

    float acc0 = 0.f, acc1 = 0.f, acc2 = 0.f, acc3 = 0.f;

    for (int c = 0; c < 4; ++c) {
        {
            const float4* __restrict__ ag =
                (const float4*)(src + (size_t)row0 * DD + c * 128);
            float4* av = (float4*)&as[0][0];
            #pragma unroll
            for (int i = 0; i < 4; ++i) {
                const int idx = tid + i * 256;
                const int r = idx >> 5, j = idx & 31;
                av[idx] = __ldg(&ag[(size_t)r * (DD / 4) + j]);
            }
        }
        {
            const float4* __restrict__ wg =
                (const float4*)(W1 + (size_t)(z * DD + c * 128) * HH);
            float4* wv = (float4*)&ws[0][0];
            #pragma unroll
            for (int i = 0; i < 4; ++i)
                wv[tid + i * 256] = __ldg(&wg[tid + i * 256]);
        }
        __syncthreads();

        #pragma unroll 8
        for (int d4 = 0; d4 < 32; ++d4) {
            const float4 a0 = *(const float4*)&as[4 * warp + 0][d4 * 4];
            const float4 a1 = *(const float4*)&as[4 * warp + 1][d4 * 4];
            const float4 a2 = *(const float4*)&as[4 * warp + 2][d4 * 4];
            const float4 a3 = *(const float4*)&as[4 * warp + 3][d4 * 4];
            const float w0  = ws[d4 * 4 + 0][h];
            const float w1v = ws[d4 * 4 + 1][h];
            const float w2v = ws[d4 * 4 + 2][h];
            const float w3v = ws[d4 * 4 + 3][h];
            acc0 = fmaf(a0.x, w0, acc0); acc0 = fmaf(a0.y, w1v, acc0);
            acc0 = fmaf(a0.z, w2v, acc0); acc0 = fmaf(a0.w, w3v, acc0);
            acc1 = fmaf(a1.x, w0, acc1); acc1 = fmaf(a1.y, w1v, acc1);
            acc1 = fmaf(a1.z, w2v, acc1); acc1 = fmaf(a1.w, w3v, acc1);
            acc2 = fmaf(a2.x, w0, acc2); acc2 = fmaf(a2.y, w1v, acc2);
            acc2 = fmaf(a2.z, w2v, acc2); acc2 = fmaf(a2.w, w3v, acc2);
            acc3 = fmaf(a3.x, w0, acc3); acc3 = fmaf(a3.y, w1v, acc3);
            acc3 = fmaf(a3.z, w2v, acc3); acc3 = fmaf(a3.w, w3v, acc3);
        }
        __syncthreads();
    }

    const float bias = (z == 0) ? __ldg(&b1[h]) : 0.f;
    float* __restrict__ dst = (z == 0) ? g_hk : g_hq;
    const int r0 = row0 + 4 * warp;
    dst[(size_t)(r0 + 0) * HH + h] = acc0 + bias;
    dst[(size_t)(r0 + 1) * HH + h] = acc1 + bias;
    dst[(size_t)(r0 + 2) * HH + h] = acc2 + bias;
    dst[(size_t)(r0 + 3) * HH + h] = acc3 + bias;
}

// ---------------------------------------------------------------------------
// Scoring v8 (dual-pipe hybrid): 64q x 32k tile, 256 thr, thread = 4q x 2k.
// Prologue stages raw hq/hk, then in-place tanh-transforms columns
// h >= H_SPLIT. Main loop:
//   h <  H_SPLIT: acc += w * tanh(hq + hk)            -> XU pipe
//   h >= H_SPLIT: acc += w * (Tq+Tk) / (1 + Tq*Tk)     -> FMA pipe
//     (reciprocal = bit-seed + 2 Newton; ~8 fma ops + 1 alu op per elem)
// Pipes overlap; each ~90% of its standalone load.
// ---------------------------------------------------------------------------
__global__ __launch_bounds__(256) void score_kernel(
    const float* __restrict__ W2, const float* __restrict__ b2,
    float* __restrict__ out)
{
    __shared__ float hqs[64][32];
    __shared__ float hks[32][33];
    __shared__ float w2s[32];

    const int b   = blockIdx.z;
    const int q0  = blockIdx.y * 64;
    const int k0  = blockIdx.x * 32;
    const int tid = threadIdx.x;

    {
        const float4* __restrict__ hq_g =
            (const float4*)(g_hq + (size_t)(b * NQv + q0) * HH);
        float4* hqv = (float4*)&hqs[0][0];
        hqv[tid]       = __ldg(&hq_g[tid]);
        hqv[tid + 256] = __ldg(&hq_g[tid + 256]);
        const float* __restrict__ hk_g = g_hk + (size_t)(b * NKv + k0) * HH;
        #pragma unroll
        for (int it = 0; it < 4; ++it) {
            const int i = tid + it * 256;
            hks[i >> 5][i & 31] = __ldg(&hk_g[i]);
        }
        if (tid < 32) w2s[tid] = __ldg(&W2[tid]);
    }
    __syncthreads();

    // In-place tanh transform of columns h >= H_SPLIT (lane == h here).
    {
        const int hh = tid & 31;
        if (hh >= H_SPLIT) {
            #pragma unroll
            for (int it = 0; it < 8; ++it) {
                const int r = (tid + it * 256) >> 5;
                hqs[r][hh] = tanh_fast(hqs[r][hh]);
            }
            #pragma unroll
            for (int it = 0; it < 4; ++it) {
                const int r = (tid + it * 256) >> 5;
                hks[r][hh] = tanh_fast(hks[r][hh]);
            }
        }
    }
    __syncthreads();

    const int kk = (tid & 15) * 2;
    const int qq = (tid >> 4) * 4;

    float a00 = 0.f, a01 = 0.f, a10 = 0.f, a11 = 0.f;
    float a20 = 0.f, a21 = 0.f, a30 = 0.f, a31 = 0.f;

    // --- XU tanh path ---
    #pragma unroll
    for (int h = 0; h < H_SPLIT; ++h) {
        const float w   = w2s[h];
        const float bk0 = hks[kk][h];
        const float bk1 = hks[kk + 1][h];
        const float q0v = hqs[qq + 0][h];
        const float q1v = hqs[qq + 1][h];
        const float q2v = hqs[qq + 2][h];
        const float q3v = hqs[qq + 3][h];
        a00 = fmaf(w, tanh_fast(q0v + bk0), a00);
        a01 = fmaf(w, tanh_fast(q0v + bk1), a01);
        a10 = fmaf(w, tanh_fast(q1v + bk0), a10);
        a11 = fmaf(w, tanh_fast(q1v + bk1), a11);
        a20 = fmaf(w, tanh_fast(q2v + bk0), a20);
        a21 = fmaf(w, tanh_fast(q2v + bk1), a21);
        a30 = fmaf(w, tanh_fast(q3v + bk0), a30);
        a31 = fmaf(w, tanh_fast(q3v + bk1), a31);
    }

    // --- FMA-pipe rational path: tanh(a+b) = (Ta+Tb)/(1+Ta*Tb) ---
    #pragma unroll
    for (int h = H_SPLIT; h < HH; ++h) {
        const float w   = w2s[h];
        const float tk0 = hks[kk][h];
        const float tk1 = hks[kk + 1][h];
        const float tq0 = hqs[qq + 0][h];
        const float tq1 = hqs[qq + 1][h];
        const float tq2 = hqs[qq + 2][h];
        const float tq3 = hqs[qq + 3][h];
        a00 = fmaf(w, (tq0 + tk0) * rcp_newton(fmaf(tq0, tk0, 1.f)), a00);
        a01 = fmaf(w, (tq0 + tk1) * rcp_newton(fmaf(tq0, tk1, 1.f)), a01);
        a10 = fmaf(w, (tq1 + tk0) * rcp_newton(fmaf(tq1, tk0, 1.f)), a10);
        a11 = fmaf(w, (tq1 + tk1) * rcp_newton(fmaf(tq1, tk1, 1.f)), a11);
        a20 = fmaf(w, (tq2 + tk0) * rcp_newton(fmaf(tq2, tk0, 1.f)), a20);
        a21 = fmaf(w, (tq2 + tk1) * rcp_newton(fmaf(tq2, tk1, 1.f)), a21);
        a30 = fmaf(w, (tq3 + tk0) * rcp_newton(fmaf(tq3, tk0, 1.f)), a30);
        a31 = fmaf(w, (tq3 + tk1) * rcp_newton(fmaf(tq3, tk1, 1.f)), a31);
    }

    const float bias = __ldg(b2);
    float* __restrict__ o =
        out + (size_t)(b * NQv + q0 + qq) * NKv + k0 + kk;
    *(float2*)(o + 0 * NKv) = make_float2(a00 + bias, a01 + bias);
    *(float2*)(o + 1 * NKv) = make_float2(a10 + bias, a11 + bias);
    *(float2*)(o + 2 * NKv) = make_float2(a20 + bias, a21 + bias);
    *(float2*)(o + 3 * NKv) = make_float2(a30 + bias, a31 + bias);
}

extern "C" void kernel_launch(void* const* d_in, const int* in_sizes, int n_in,
                              void* d_out, int out_size)
{
    const float* keys    = (const float*)d_in[0];
    const float* queries = (const float*)d_in[1];
    const float* W1      = (const float*)d_in[2];
    const float* b1      = (const float*)d_in[3];
    const float* W2      = (const float*)d_in[4];
    const float* b2      = (const float*)d_in[5];
    float* out = (float*)d_out;

    proj_kernel<<<dim3(64, 2, 1), 256>>>(keys, queries, W1, b1);
    score_kernel<<<dim3(NKv / 32, NQv / 64, BB), 256>>>(W2, b2, out);
}

// round 9
// speedup vs baseline: 1.0503x; 1.0503x over previous
#include <cuda_runtime.h>

#define BB 2
#define NQv 1024
#define NKv 1024
#define DD 512
#define HH 32

// Rational-path column predicate: h ∈ {4,9,14,19,24,29} (6 of 32).
#define IS_RAT(h) (((h) % 5) == 4)

// Split-K partial buffers (no cudaMalloc allowed). f32.
__device__ __align__(16) float g_hkp[2][BB * NKv * HH];
__device__ __align__(16) float g_hqp[2][BB * NQv * HH];

__device__ __forceinline__ float tanh_fast(float x) {
    float y; asm("tanh.approx.f32 %0, %1;" : "=f"(y) : "f"(x)); return y;
}
// FMA-pipe reciprocal: magic-seed (~3.4% rel) + 2 Newton -> ~1.4e-6 rel.
__device__ __forceinline__ float rcp_newton(float d) {
    float r = __uint_as_float(0x7EF311C3u - __float_as_uint(d));
    r = r * fmaf(-d, r, 2.0f);
    r = r * fmaf(-d, r, 2.0f);
    return r;
}

// ---------------------------------------------------------------------------
// Projection (R7 split-K config, measured best): grid (64,2,2) = 256 blocks.
// Block: 32 rows x 256 d (two 128-d chunks); thread = 4 rows x 1 h.
// Partials to gmem; score kernel sums the two halves during staging.
// ---------------------------------------------------------------------------
__global__ __launch_bounds__(256) void proj_kernel(
    const float* __restrict__ keys, const float* __restrict__ queries,
    const float* __restrict__ W1, const float* __restrict__ b1)
{
    __shared__ float as[32][128];
    __shared__ float ws[128][32];

    const int z    = blockIdx.y;
    const int ks   = blockIdx.z;
    const int tid  = threadIdx.x;
    const int h    = tid & 31;
    const int warp = tid >> 5;
    const int row0 = blockIdx.x * 32;
    const float* __restrict__ src = z ? queries : keys;

    float acc0 = 0.f, acc1 = 0.f, acc2 = 0.f, acc3 = 0.f;

    #pragma unroll
    for (int cc = 0; cc < 2; ++cc) {
        const int dchunk = ks * 256 + cc * 128;
        {
            const float4* __restrict__ ag =
                (const float4*)(src + (size_t)row0 * DD + dchunk);
            float4* av = (float4*)&as[0][0];
            #pragma unroll
            for (int i = 0; i < 4; ++i) {
                const int idx = tid + i * 256;
                const int r = idx >> 5, j = idx & 31;
                av[idx] = __ldg(&ag[(size_t)r * (DD / 4) + j]);
            }
        }
        {
            const float4* __restrict__ wg =
                (const float4*)(W1 + (size_t)(z * DD + dchunk) * HH);
            float4* wv = (float4*)&ws[0][0];
            #pragma unroll
            for (int i = 0; i < 4; ++i)
                wv[tid + i * 256] = __ldg(&wg[tid + i * 256]);
        }
        __syncthreads();

        #pragma unroll 8
        for (int d4 = 0; d4 < 32; ++d4) {
            const float4 a0 = *(const float4*)&as[4 * warp + 0][d4 * 4];
            const float4 a1 = *(const float4*)&as[4 * warp + 1][d4 * 4];
            const float4 a2 = *(const float4*)&as[4 * warp + 2][d4 * 4];
            const float4 a3 = *(const float4*)&as[4 * warp + 3][d4 * 4];
            const float w0  = ws[d4 * 4 + 0][h];
            const float w1v = ws[d4 * 4 + 1][h];
            const float w2v = ws[d4 * 4 + 2][h];
            const float w3v = ws[d4 * 4 + 3][h];
            acc0 = fmaf(a0.x, w0, acc0); acc0 = fmaf(a0.y, w1v, acc0);
            acc0 = fmaf(a0.z, w2v, acc0); acc0 = fmaf(a0.w, w3v, acc0);
            acc1 = fmaf(a1.x, w0, acc1); acc1 = fmaf(a1.y, w1v, acc1);
            acc1 = fmaf(a1.z, w2v, acc1); acc1 = fmaf(a1.w, w3v, acc1);
            acc2 = fmaf(a2.x, w0, acc2); acc2 = fmaf(a2.y, w1v, acc2);
            acc2 = fmaf(a2.z, w2v, acc2); acc2 = fmaf(a2.w, w3v, acc2);
            acc3 = fmaf(a3.x, w0, acc3); acc3 = fmaf(a3.y, w1v, acc3);
            acc3 = fmaf(a3.z, w2v, acc3); acc3 = fmaf(a3.w, w3v, acc3);
        }
        __syncthreads();
    }

    const float bias = (z == 0 && ks == 0) ? __ldg(&b1[h]) : 0.f;
    float* __restrict__ dst = (z == 0) ? g_hkp[ks] : g_hqp[ks];
    const int r0 = row0 + 4 * warp;
    dst[(size_t)(r0 + 0) * HH + h] = acc0 + bias;
    dst[(size_t)(r0 + 1) * HH + h] = acc1 + bias;
    dst[(size_t)(r0 + 2) * HH + h] = acc2 + bias;
    dst[(size_t)(r0 + 3) * HH + h] = acc3 + bias;
}

// ---------------------------------------------------------------------------
// Scoring v9 (INTERLEAVED dual-pipe hybrid): 64q x 32k tile, thread = 4q x 2k.
// Staging sums split-K partials, then tanh-transforms the 6 rational columns
// in place. ONE fused unrolled h-loop:
//   !IS_RAT(h): acc += w * tanh(hq+hk)              -> XU pipe  (26 cols)
//   IS_RAT(h) : acc += w * (Tq+Tk)/(1+Tq*Tk)         -> FMA pipe ( 6 cols)
// Both op types live in the same instruction window -> pipes overlap.
// Budget/warp: XU 1664 cyc vs FMA 1600 cyc (vs 2048 XU-only).
// ---------------------------------------------------------------------------
__global__ __launch_bounds__(256) void score_kernel(
    const float* __restrict__ W2, const float* __restrict__ b2,
    float* __restrict__ out)
{
    __shared__ float hqs[64][32];
    __shared__ float hks[32][33];
    __shared__ float w2s[32];

    const int b   = blockIdx.z;
    const int q0  = blockIdx.y * 64;
    const int k0  = blockIdx.x * 32;
    const int tid = threadIdx.x;

    {
        const size_t qoff = (size_t)(b * NQv + q0) * HH;
        const float4* __restrict__ hq0 = (const float4*)(g_hqp[0] + qoff);
        const float4* __restrict__ hq1 = (const float4*)(g_hqp[1] + qoff);
        float4* hqv = (float4*)&hqs[0][0];
        #pragma unroll
        for (int it = 0; it < 2; ++it) {
            const int i = tid + it * 256;
            const float4 v0 = __ldg(&hq0[i]);
            const float4 v1 = __ldg(&hq1[i]);
            hqv[i] = make_float4(v0.x + v1.x, v0.y + v1.y,
                                 v0.z + v1.z, v0.w + v1.w);
        }
        const size_t koff = (size_t)(b * NKv + k0) * HH;
        const float* __restrict__ hk0 = g_hkp[0] + koff;
        const float* __restrict__ hk1 = g_hkp[1] + koff;
        #pragma unroll
        for (int it = 0; it < 4; ++it) {
            const int i = tid + it * 256;
            hks[i >> 5][i & 31] = __ldg(&hk0[i]) + __ldg(&hk1[i]);
        }
        if (tid < 32) w2s[tid] = __ldg(&W2[tid]);
    }
    __syncthreads();

    // In-place tanh transform of the 6 rational columns (lane == column).
    {
        const int hh = tid & 31;
        if (IS_RAT(hh)) {
            #pragma unroll
            for (int it = 0; it < 8; ++it) {
                const int r = (tid + it * 256) >> 5;
                hqs[r][hh] = tanh_fast(hqs[r][hh]);
            }
            #pragma unroll
            for (int it = 0; it < 4; ++it) {
                const int r = (tid + it * 256) >> 5;
                hks[r][hh] = tanh_fast(hks[r][hh]);
            }
        }
    }
    __syncthreads();

    const int kk = (tid & 15) * 2;
    const int qq = (tid >> 4) * 4;

    float a00 = 0.f, a01 = 0.f, a10 = 0.f, a11 = 0.f;
    float a20 = 0.f, a21 = 0.f, a30 = 0.f, a31 = 0.f;

    #pragma unroll
    for (int h = 0; h < HH; ++h) {
        const float w  = w2s[h];
        const float k0v = hks[kk][h];
        const float k1v = hks[kk + 1][h];
        const float v0 = hqs[qq + 0][h];
        const float v1 = hqs[qq + 1][h];
        const float v2 = hqs[qq + 2][h];
        const float v3 = hqs[qq + 3][h];
        if (IS_RAT(h)) {   // FMA-pipe rational path (values are Tq/Tk)
            a00 = fmaf(w, (v0 + k0v) * rcp_newton(fmaf(v0, k0v, 1.f)), a00);
            a01 = fmaf(w, (v0 + k1v) * rcp_newton(fmaf(v0, k1v, 1.f)), a01);
            a10 = fmaf(w, (v1 + k0v) * rcp_newton(fmaf(v1, k0v, 1.f)), a10);
            a11 = fmaf(w, (v1 + k1v) * rcp_newton(fmaf(v1, k1v, 1.f)), a11);
            a20 = fmaf(w, (v2 + k0v) * rcp_newton(fmaf(v2, k0v, 1.f)), a20);
            a21 = fmaf(w, (v2 + k1v) * rcp_newton(fmaf(v2, k1v, 1.f)), a21);
            a30 = fmaf(w, (v3 + k0v) * rcp_newton(fmaf(v3, k0v, 1.f)), a30);
            a31 = fmaf(w, (v3 + k1v) * rcp_newton(fmaf(v3, k1v, 1.f)), a31);
        } else {           // XU tanh path (values are raw hq/hk)
            a00 = fmaf(w, tanh_fast(v0 + k0v), a00);
            a01 = fmaf(w, tanh_fast(v0 + k1v), a01);
            a10 = fmaf(w, tanh_fast(v1 + k0v), a10);
            a11 = fmaf(w, tanh_fast(v1 + k1v), a11);
            a20 = fmaf(w, tanh_fast(v2 + k0v), a20);
            a21 = fmaf(w, tanh_fast(v2 + k1v), a21);
            a30 = fmaf(w, tanh_fast(v3 + k0v), a30);
            a31 = fmaf(w, tanh_fast(v3 + k1v), a31);
        }
    }

    const float bias = __ldg(b2);
    float* __restrict__ o =
        out + (size_t)(b * NQv + q0 + qq) * NKv + k0 + kk;
    *(float2*)(o + 0 * NKv) = make_float2(a00 + bias, a01 + bias);
    *(float2*)(o + 1 * NKv) = make_float2(a10 + bias, a11 + bias);
    *(float2*)(o + 2 * NKv) = make_float2(a20 + bias, a21 + bias);
    *(float2*)(o + 3 * NKv) = make_float2(a30 + bias, a31 + bias);
}

extern "C" void kernel_launch(void* const* d_in, const int* in_sizes, int n_in,
                              void* d_out, int out_size)
{
    const float* keys    = (const float*)d_in[0];
    const float* queries = (const float*)d_in[1];
    const float* W1      = (const float*)d_in[2];
    const float* b1      = (const float*)d_in[3];
    const float* W2      = (const float*)d_in[4];
    const float* b2      = (const float*)d_in[5];
    float* out = (float*)d_out;

    proj_kernel<<<dim3(64, 2, 2), 256>>>(keys, queries, W1, b1);
    score_kernel<<<dim3(NKv / 32, NQv / 64, BB), 256>>>(W2, b2, out);
}